// round 15
// baseline (speedup 1.0000x reference)
#include <cuda_runtime.h>
#include <cuda_fp16.h>
#include <cstdint>

// Problem constants
#define B_  8
#define L_  4096
#define N_  128
#define F_  128
#define H_  8
#define TV_ 256
#define BOT_ 256
#define FFN_ 2048
#define INV_C 0.9995003746877732f  // 1/sqrt(1+1e-3)
#define L2E  1.4426950408889634f

#define MPIX (B_*L_)   // 32768
#define MMEM (B_*N_)   // 1024
#define NSPLIT 9       // 8 pixel-key splits + 1 mem-key split

// -------------------- scratch (device globals; no allocation) --------------------
__device__ __half g_pixinH[MPIX*F_];
__device__ __half g_meminH[MMEM*F_];
__device__ __half g_pixH [MPIX*BOT_];
__device__ __half g_pqkvH[(size_t)MPIX*512];
__device__ __half g_memH [MMEM*BOT_];
__device__ __half g_mqkvH[MMEM*512];
__device__ __half g_retmemH[MMEM*TV_];
__device__ float  g_memout[MMEM*F_];
__device__ __half g_memoutH[MMEM*F_];
__device__ __half g_ffnH [MMEM*FFN_];
__device__ __half g_pretH[(size_t)MPIX*TV_];
__device__ float  g_mpart[64*NSPLIT*34*128];
__device__ __half g_wth[917504];        // transposed fp16 weights
__device__ float  g_skpart[8*MMEM*F_];  // split-K partials for ffn2

// offsets into g_wth
#define O_PIX1 0
#define O_MEM1 32768
#define O_PQKV 65536
#define O_MQKV 196608
#define O_MEM3 327680
#define O_PIX3 360448
#define O_FFN1 393216
#define O_FFN2 655360

// -------------------- streams/events for capture fork-join --------------------
struct ForkCtx {
    cudaStream_t s2;
    cudaEvent_t evF, evJ;
    ForkCtx() {
        cudaStreamCreate(&s2);
        cudaEventCreateWithFlags(&evF, cudaEventDisableTiming);
        cudaEventCreateWithFlags(&evJ, cudaEventDisableTiming);
    }
};
static ForkCtx g_fork;

// -------------------- fast math --------------------
__device__ __forceinline__ float ex2a(float x){ float r; asm("ex2.approx.f32 %0, %1;" : "=f"(r):"f"(x)); return r; }
__device__ __forceinline__ float rcpa(float x){ float r; asm("rcp.approx.f32 %0, %1;" : "=f"(r):"f"(x)); return r; }
__device__ __forceinline__ uint32_t f22h(float a, float b){
    uint32_t r;
    asm("cvt.rn.f16x2.f32 %0, %1, %2;" : "=r"(r) : "f"(b), "f"(a));
    return r;
}
__device__ __forceinline__ uint32_t smem_u32(const void* p){
    uint32_t a; asm("{ .reg .u64 t; cvta.to.shared.u64 t, %1; cvt.u32.u64 %0, t; }" : "=r"(a) : "l"(p));
    return a;
}
__device__ __forceinline__ void cpa16(uint32_t s, const void* g){
    asm volatile("cp.async.ca.shared.global [%0], [%1], 16;" :: "r"(s), "l"(g));
}
#define CP_COMMIT() asm volatile("cp.async.commit_group;" ::: "memory")

__device__ __forceinline__ void ldsm4(uint32_t* r, uint32_t addr){
    asm volatile("ldmatrix.sync.aligned.m8n8.x4.shared.b16 {%0,%1,%2,%3}, [%4];"
        : "=r"(r[0]), "=r"(r[1]), "=r"(r[2]), "=r"(r[3]) : "r"(addr));
}
__device__ __forceinline__ void ldsm4t(uint32_t* r, uint32_t addr){
    asm volatile("ldmatrix.sync.aligned.m8n8.x4.trans.shared.b16 {%0,%1,%2,%3}, [%4];"
        : "=r"(r[0]), "=r"(r[1]), "=r"(r[2]), "=r"(r[3]) : "r"(addr));
}

// fp16 mma: D[16x8] += A[16x16] * B[16x8]
__device__ __forceinline__ void mma16(float* d, const uint32_t* a, uint32_t b0, uint32_t b1){
    asm volatile("mma.sync.aligned.m16n8k16.row.col.f32.f16.f16.f32 "
        "{%0,%1,%2,%3}, {%4,%5,%6,%7}, {%8,%9}, {%0,%1,%2,%3};"
        : "+f"(d[0]), "+f"(d[1]), "+f"(d[2]), "+f"(d[3])
        : "r"(a[0]), "r"(a[1]), "r"(a[2]), "r"(a[3]), "r"(b0), "r"(b1));
}

// -------------------- prep: input cvt + weight transpose, one launch --------------------
struct WTd { const float* in; __half* out; int K; int N; int tiles; };
struct WTargs { WTd d[8]; };

__global__ void __launch_bounds__(256) prep_all(
        WTargs a,
        const float* __restrict__ pin, __half* __restrict__ pinH, int na,
        const float* __restrict__ min_, __half* __restrict__ minH, int ncvt) {
    __shared__ float t[32][33];
    if ((int)blockIdx.x < ncvt) {
        const int q = (blockIdx.x * 256 + threadIdx.x) * 4;
        if (q < na) {
            float4 v = *(const float4*)(pin + q);
            uint2 u = {f22h(v.x, v.y), f22h(v.z, v.w)};
            *(uint2*)(pinH + q) = u;
        } else {
            const int p = q - na;
            float4 v = *(const float4*)(min_ + p);
            uint2 u = {f22h(v.x, v.y), f22h(v.z, v.w)};
            *(uint2*)(minH + p) = u;
        }
        return;
    }
    int tile = blockIdx.x - ncvt;
    int i = 0;
    while (i < 7 && tile >= a.d[i].tiles) { tile -= a.d[i].tiles; i++; }
    const float* in = a.d[i].in;
    __half* out = a.d[i].out;
    const int K = a.d[i].K, Nn = a.d[i].N;
    const int ntx = Nn >> 5;
    const int bx = tile % ntx, by = tile / ntx;
    const int tx = threadIdx.x & 31, ty = threadIdx.x >> 5;
    #pragma unroll
    for (int j = 0; j < 4; j++)
        t[ty + j * 8][tx] = in[(size_t)(by * 32 + ty + j * 8) * Nn + bx * 32 + tx];
    __syncthreads();
    #pragma unroll
    for (int j = 0; j < 4; j++)
        out[(size_t)(bx * 32 + ty + j * 8) * K + by * 32 + tx] = __float2half_rn(t[tx][ty + j * 8]);
}

// -------------------- fp16 mma GEMM: cp.async + ldmatrix --------------------
template<bool RELU, bool RES, bool PARTIAL, int OH, bool DUAL>
__global__ void __launch_bounds__(256, 2) gemm_h(
        const __half* __restrict__ A, const __half* __restrict__ Bt,
        const float* __restrict__ bn, const float* __restrict__ res,
        float* __restrict__ C, __half* __restrict__ Ch, int M, int Nn, int K, int lda,
        const __half* __restrict__ A2, const __half* __restrict__ Bt2,
        const float* __restrict__ bn2, float* __restrict__ C2, __half* __restrict__ Ch2,
        int ysplit) {
    extern __shared__ __half smh[];
    float* bns = (float*)(smh + 32768);
    const uint32_t sAu = smem_u32(smh);
    const uint32_t sBu = sAu + 32768;
    const int tid = threadIdx.x;
    const int w = tid >> 5, lane = tid & 31;
    const int lx = lane & 3;
    const int wm = w >> 2, wn = w & 3;
    const int n0 = blockIdx.x * 128;

    const __half* Abase = A;
    const __half* Btb = Bt;
    const float* bnp = bn;
    float* Cp_ = C;
    __half* Chp = Ch;
    int by = blockIdx.y;
    if (DUAL && by >= ysplit) {
        by -= ysplit;
        Abase = A2; Btb = Bt2; bnp = bn2; Cp_ = C2; Chp = Ch2;
    }
    const int m0 = by * 128;
    const int kbeg = PARTIAL ? blockIdx.z * K : 0;

    if (!PARTIAL && tid < 128) {
        bns[tid]       = bnp[n0 + tid] * INV_C;
        bns[128 + tid] = bnp[Nn + n0 + tid];
    }

    const int r = tid >> 1, hh = tid & 1;
    const __half* Ap = Abase + (size_t)(m0 + r) * lda + kbeg + hh * 32;
    const __half* Bp = Btb + (size_t)(n0 + r) * lda + kbeg + hh * 32;
    uint32_t stA[4], stB[4];
    #pragma unroll
    for (int j = 0; j < 4; j++) {
        const uint32_t u = (uint32_t)(((hh * 4 + j) ^ (r & 7)) << 3);
        stA[j] = sAu + (uint32_t)(r * 64 + u) * 2;
        stB[j] = sBu + (uint32_t)(r * 64 + u) * 2;
    }

    const int sub = lane >> 3;
    const int a_ro = (sub & 1) * 8 + (lane & 7);
    const int a_c  = sub >> 1;
    const int b_ro = (sub >> 1) * 8 + (lane & 7);
    const int b_c  = sub & 1;
    uint32_t rowA_b[4]; int rpA[4];
    #pragma unroll
    for (int mt = 0; mt < 4; mt++) {
        const int row = wm * 64 + mt * 16 + a_ro;
        rowA_b[mt] = (uint32_t)row * 128;
        rpA[mt] = row & 7;
    }
    uint32_t rowB_b[2]; int rpB[2];
    #pragma unroll
    for (int p = 0; p < 2; p++) {
        const int n = wn * 32 + p * 16 + b_ro;
        rowB_b[p] = (uint32_t)n * 128;
        rpB[p] = n & 7;
    }

    const int KB = K >> 6;
    #pragma unroll
    for (int j = 0; j < 4; j++) {
        cpa16(stA[j], Ap + j * 8);
        cpa16(stB[j], Bp + j * 8);
    }
    CP_COMMIT();

    float acc[4][4][4];
    #pragma unroll
    for (int a = 0; a < 4; a++)
        #pragma unroll
        for (int b = 0; b < 4; b++)
            #pragma unroll
            for (int c = 0; c < 4; c++) acc[a][b][c] = 0.0f;

    for (int kb = 0; kb < KB; kb++) {
        if (kb + 1 < KB) {
            const uint32_t bo = (uint32_t)(((kb + 1) & 1) * 16384);
            #pragma unroll
            for (int j = 0; j < 4; j++) {
                cpa16(stA[j] + bo, Ap + (size_t)(kb + 1) * 64 + j * 8);
                cpa16(stB[j] + bo, Bp + (size_t)(kb + 1) * 64 + j * 8);
            }
            CP_COMMIT();
            asm volatile("cp.async.wait_group 1;" ::: "memory");
        } else {
            asm volatile("cp.async.wait_group 0;" ::: "memory");
        }
        __syncthreads();

        const uint32_t bufA = sAu + (uint32_t)((kb & 1) * 16384);
        const uint32_t bufB = sBu + (uint32_t)((kb & 1) * 16384);
        #pragma unroll
        for (int kt = 0; kt < 4; kt++) {
            const int ub = 2 * kt;
            uint32_t af[4][4], bf[4][2];
            #pragma unroll
            for (int p = 0; p < 2; p++) {
                uint32_t rr[4];
                ldsm4(rr, bufB + rowB_b[p] + (uint32_t)(((ub + b_c) ^ rpB[p]) << 4));
                bf[2*p][0]   = rr[0]; bf[2*p][1]   = rr[1];
                bf[2*p+1][0] = rr[2]; bf[2*p+1][1] = rr[3];
            }
            #pragma unroll
            for (int mt = 0; mt < 4; mt++)
                ldsm4(af[mt], bufA + rowA_b[mt] + (uint32_t)(((ub + a_c) ^ rpA[mt]) << 4));
            #pragma unroll
            for (int mt = 0; mt < 4; mt++)
                #pragma unroll
                for (int nt = 0; nt < 4; nt++)
                    mma16(acc[mt][nt], af[mt], bf[nt][0], bf[nt][1]);
        }
        __syncthreads();
    }

    const int ly = lane >> 2;
    if (PARTIAL) {
        float* Cpz = Cp_ + (size_t)blockIdx.z * M * Nn;
        #pragma unroll
        for (int mt = 0; mt < 4; mt++) {
            const int rr = m0 + wm * 64 + mt * 16 + ly;
            #pragma unroll
            for (int nt = 0; nt < 4; nt++) {
                const int cc = n0 + wn * 32 + nt * 8 + lx * 2;
                float2 v0 = {acc[mt][nt][0], acc[mt][nt][1]};
                float2 v1 = {acc[mt][nt][2], acc[mt][nt][3]};
                *(float2*)&Cpz[(size_t)rr * Nn + cc] = v0;
                *(float2*)&Cpz[(size_t)(rr + 8) * Nn + cc] = v1;
            }
        }
    } else {
        #pragma unroll
        for (int mt = 0; mt < 4; mt++) {
            const int rr = m0 + wm * 64 + mt * 16 + ly;
            #pragma unroll
            for (int nt = 0; nt < 4; nt++) {
                const int lc = wn * 32 + nt * 8 + lx * 2;
                const int cc = n0 + lc;
                const float g0 = bns[lc], g1 = bns[lc + 1];
                const float b0 = bns[128 + lc], b1 = bns[128 + lc + 1];
                float2 v0, v1;
                v0.x = fmaf(acc[mt][nt][0], g0, b0);
                v0.y = fmaf(acc[mt][nt][1], g1, b1);
                v1.x = fmaf(acc[mt][nt][2], g0, b0);
                v1.y = fmaf(acc[mt][nt][3], g1, b1);
                const size_t i0 = (size_t)rr * Nn + cc;
                const size_t i1 = (size_t)(rr + 8) * Nn + cc;
                if (RES) {
                    float2 r0 = *(const float2*)&res[i0];
                    float2 r1 = *(const float2*)&res[i1];
                    v0.x += r0.x; v0.y += r0.y; v1.x += r1.x; v1.y += r1.y;
                }
                if (RELU) {
                    v0.x = fmaxf(v0.x, 0.0f); v0.y = fmaxf(v0.y, 0.0f);
                    v1.x = fmaxf(v1.x, 0.0f); v1.y = fmaxf(v1.y, 0.0f);
                }
                if (OH == 0 || OH == 2) {
                    *(float2*)&Cp_[i0] = v0;
                    *(float2*)&Cp_[i1] = v1;
                }
                if (OH >= 1) {
                    *(uint32_t*)&Chp[i0] = f22h(v0.x, v0.y);
                    *(uint32_t*)&Chp[i1] = f22h(v1.x, v1.y);
                }
            }
        }
    }
}

#define GEMM_SMEM (65536 + 1024)

// split-K reduce for ffn2
__global__ void __launch_bounds__(256) sk_reduce(
        const float* __restrict__ part, const float* __restrict__ bn,
        const float* __restrict__ res, float* __restrict__ out, int M, int SK) {
    const int idx = blockIdx.x * 256 + threadIdx.x;
    const int c = idx & 127;
    float s = 0.0f;
    for (int k = 0; k < SK; k++) s += part[(size_t)k * M * 128 + idx];
    float v = fmaf(s, bn[c] * INV_C, bn[128 + c]) + res[idx];
    out[idx] = fmaxf(v, 0.0f);
}

// ==================== shared attention helpers (fp16 KV tile) ====================
// sKV layout: 128 key rows x 64 halves (128B), 16B-unit XOR swizzle u^(row&7).
// units 0-1: K dims 0..15; units 2-5: V dims 0..31.

// stage one 128-key tile from fp16 qkv rows (stride 512), head h
__device__ __forceinline__ void stage_kv(__half* sKV, const __half* kvbase, int h, int tid){
    const int row = tid >> 1, part = tid & 1;
    const __half* src = kvbase + (size_t)row * 512;
    char* dst = (char*)sKV + row * 128;
    if (part == 0) {
        uint4 k0 = *(const uint4*)(src + 128 + h * 16);
        uint4 k1 = *(const uint4*)(src + 128 + h * 16 + 8);
        uint4 v0 = *(const uint4*)(src + 256 + h * 32);
        *(uint4*)(dst + (((0 ^ (row & 7))) << 4)) = k0;
        *(uint4*)(dst + (((1 ^ (row & 7))) << 4)) = k1;
        *(uint4*)(dst + (((2 ^ (row & 7))) << 4)) = v0;
    } else {
        uint4 v1 = *(const uint4*)(src + 256 + h * 32 + 8);
        uint4 v2 = *(const uint4*)(src + 256 + h * 32 + 16);
        uint4 v3 = *(const uint4*)(src + 256 + h * 32 + 24);
        *(uint4*)(dst + (((3 ^ (row & 7))) << 4)) = v1;
        *(uint4*)(dst + (((4 ^ (row & 7))) << 4)) = v2;
        *(uint4*)(dst + (((5 ^ (row & 7))) << 4)) = v3;
    }
}

// load Q fragment (16 rows q0..q0+15, dims h*16..+15) from fp16 rows stride 512
__device__ __forceinline__ void load_q(uint32_t* aq, const __half* qbase, int q0, int h, int lane){
    const int ly = lane >> 2, lx = lane & 3;
    const __half* r0 = qbase + (size_t)(q0 + ly) * 512 + h * 16;
    const __half* r1 = r0 + (size_t)8 * 512;
    aq[0] = *(const uint32_t*)(r0 + 2 * lx);
    aq[1] = *(const uint32_t*)(r1 + 2 * lx);
    aq[2] = *(const uint32_t*)(r0 + 2 * lx + 8);
    aq[3] = *(const uint32_t*)(r1 + 2 * lx + 8);
}

// S[16][4] = Q @ K^T over the 128-key tile
__device__ __forceinline__ void qk_mma(float (*S)[4], const uint32_t* aq, uint32_t sKVu, int lane){
    const int key_off = ((lane >> 4) << 3) + (lane & 7);
    const int unit = (lane >> 3) & 1;
    #pragma unroll
    for (int p = 0; p < 8; p++) {
        const int key = p * 16 + key_off;
        uint32_t rr[4];
        ldsm4(rr, sKVu + (uint32_t)key * 128 + (uint32_t)((unit ^ (key & 7)) << 4));
        mma16(S[2*p],   aq, rr[0], rr[1]);
        mma16(S[2*p+1], aq, rr[2], rr[3]);
    }
}

// O[4][4] += P(S packed fp16) @ V over the 128-key tile
__device__ __forceinline__ void pv_mma(float (*O)[4], const float (*S)[4], uint32_t sKVu, int lane){
    const int key_off = ((lane >> 3) & 1) * 8 + (lane & 7);
    const int ug = lane >> 4;  // 0/1
    #pragma unroll
    for (int j = 0; j < 8; j++) {
        uint32_t as[4];
        as[0] = f22h(S[2*j][0],   S[2*j][1]);
        as[1] = f22h(S[2*j][2],   S[2*j][3]);
        as[2] = f22h(S[2*j+1][0], S[2*j+1][1]);
        as[3] = f22h(S[2*j+1][2], S[2*j+1][3]);
        const int key = j * 16 + key_off;
        uint32_t rr[4];
        const int u0 = 2 + ug;
        ldsm4t(rr, sKVu + (uint32_t)key * 128 + (uint32_t)((u0 ^ (key & 7)) << 4));
        mma16(O[0], as, rr[0], rr[1]);
        mma16(O[1], as, rr[2], rr[3]);
        const int u1 = 4 + ug;
        ldsm4t(rr, sKVu + (uint32_t)key * 128 + (uint32_t)((u1 ^ (key & 7)) << 4));
        mma16(O[2], as, rr[0], rr[1]);
        mma16(O[3], as, rr[2], rr[3]);
    }
}

// -------------------- memory-path attention: tensor-core flash split (fp16) -----------
__global__ void __launch_bounds__(256) mem_attn_split_tc(
        const __half* __restrict__ pqkvH, const __half* __restrict__ mqkvH,
        const float* __restrict__ bn_sim, float* __restrict__ part) {
    const int s = blockIdx.x, h = blockIdx.y, b = blockIdx.z;
    const int tid = threadIdx.x;
    const int w = tid >> 5, lane = tid & 31;
    const int ly = lane >> 2, lx = lane & 3;

    __shared__ __half sKV[128 * 64];
    const uint32_t sKVu = smem_u32(sKV);

    const int q0 = w * 16;
    uint32_t aq[4];
    load_q(aq, mqkvH + (size_t)b * 128 * 512, q0, h, lane);
    const float gs = bn_sim[h] * INV_C;
    const float gb = bn_sim[8 + h];

    float m0 = -1e30f, m1 = -1e30f, li0 = 0.0f, li1 = 0.0f;
    float O[4][4];
    #pragma unroll
    for (int i = 0; i < 4; i++) O[i][0] = O[i][1] = O[i][2] = O[i][3] = 0.0f;

    const int ntiles = (s < 8) ? 4 : 1;
    for (int t = 0; t < ntiles; t++) {
        const __half* kvbase = (s < 8)
            ? pqkvH + (size_t)(b * 4096 + s * 512 + t * 128) * 512
            : mqkvH + (size_t)(b * 128) * 512;
        stage_kv(sKV, kvbase, h, tid);
        __syncthreads();

        float S[16][4];
        #pragma unroll
        for (int nt = 0; nt < 16; nt++)
            S[nt][0] = S[nt][1] = S[nt][2] = S[nt][3] = 0.0f;
        qk_mma(S, aq, sKVu, lane);

        float lm0 = -1e30f, lm1 = -1e30f;
        #pragma unroll
        for (int nt = 0; nt < 16; nt++) {
            S[nt][0] = fmaf(S[nt][0], gs, gb);
            S[nt][1] = fmaf(S[nt][1], gs, gb);
            S[nt][2] = fmaf(S[nt][2], gs, gb);
            S[nt][3] = fmaf(S[nt][3], gs, gb);
            lm0 = fmaxf(lm0, fmaxf(S[nt][0], S[nt][1]));
            lm1 = fmaxf(lm1, fmaxf(S[nt][2], S[nt][3]));
        }
        lm0 = fmaxf(lm0, __shfl_xor_sync(0xffffffffu, lm0, 1));
        lm0 = fmaxf(lm0, __shfl_xor_sync(0xffffffffu, lm0, 2));
        lm1 = fmaxf(lm1, __shfl_xor_sync(0xffffffffu, lm1, 1));
        lm1 = fmaxf(lm1, __shfl_xor_sync(0xffffffffu, lm1, 2));
        const float nm0 = fmaxf(m0, lm0), nm1 = fmaxf(m1, lm1);
        const float c0 = ex2a((m0 - nm0) * L2E);
        const float c1 = ex2a((m1 - nm1) * L2E);
        m0 = nm0; m1 = nm1;
        li0 *= c0; li1 *= c1;
        #pragma unroll
        for (int nt = 0; nt < 4; nt++) {
            O[nt][0] *= c0; O[nt][1] *= c0;
            O[nt][2] *= c1; O[nt][3] *= c1;
        }
        #pragma unroll
        for (int nt = 0; nt < 16; nt++) {
            S[nt][0] = ex2a((S[nt][0] - nm0) * L2E);
            S[nt][1] = ex2a((S[nt][1] - nm0) * L2E);
            S[nt][2] = ex2a((S[nt][2] - nm1) * L2E);
            S[nt][3] = ex2a((S[nt][3] - nm1) * L2E);
            li0 += S[nt][0] + S[nt][1];
            li1 += S[nt][2] + S[nt][3];
        }
        pv_mma(O, S, sKVu, lane);
        __syncthreads();
    }

    li0 += __shfl_xor_sync(0xffffffffu, li0, 1);
    li0 += __shfl_xor_sync(0xffffffffu, li0, 2);
    li1 += __shfl_xor_sync(0xffffffffu, li1, 1);
    li1 += __shfl_xor_sync(0xffffffffu, li1, 2);

    float* base = part + (size_t)(((b * 8 + h) * NSPLIT + s) * 34) * 128;
    const int r0 = q0 + ly, r1 = q0 + ly + 8;
    if (lx == 0) {
        base[r0] = m0;        base[r1] = m1;
        base[128 + r0] = li0; base[128 + r1] = li1;
    }
    #pragma unroll
    for (int nt = 0; nt < 4; nt++) {
        const int c = nt * 8 + 2 * lx;
        base[(2 + c)     * 128 + r0] = O[nt][0];
        base[(2 + c + 1) * 128 + r0] = O[nt][1];
        base[(2 + c)     * 128 + r1] = O[nt][2];
        base[(2 + c + 1) * 128 + r1] = O[nt][3];
    }
}

// combine: outputs fp16 retmem
__global__ void __launch_bounds__(128) mem_attn_combine(
        const float* __restrict__ part, const float* __restrict__ bn_ret,
        __half* __restrict__ retmemH) {
    const int bh = blockIdx.x;
    const int n = threadIdx.x;
    const int b = bh >> 3, h = bh & 7;
    float M = -1e30f;
    #pragma unroll
    for (int s = 0; s < NSPLIT; s++)
        M = fmaxf(M, part[(size_t)((bh * NSPLIT + s) * 34) * 128 + n]);
    float Lsum = 0.0f;
    float acc[32] = {};
    #pragma unroll
    for (int s = 0; s < NSPLIT; s++) {
        const float* base = part + (size_t)((bh * NSPLIT + s) * 34) * 128;
        float wgt = ex2a((base[n] - M) * L2E);
        Lsum = fmaf(base[128 + n], wgt, Lsum);
        #pragma unroll
        for (int d = 0; d < 32; d++)
            acc[d] = fmaf(wgt, base[(2 + d) * 128 + n], acc[d]);
    }
    float inv = rcpa(Lsum);
    inv = inv * (2.0f - Lsum * inv);
    __half* out = retmemH + (size_t)(b * 128 + n) * 256 + h * 32;
    #pragma unroll
    for (int d = 0; d < 16; d++) {
        float r0 = acc[2*d]   * inv;
        float r1 = acc[2*d+1] * inv;
        r0 = fmaxf(fmaf(r0, bn_ret[h * 32 + 2*d]   * INV_C, bn_ret[256 + h * 32 + 2*d]),   0.0f);
        r1 = fmaxf(fmaf(r1, bn_ret[h * 32 + 2*d+1] * INV_C, bn_ret[256 + h * 32 + 2*d+1]), 0.0f);
        *(uint32_t*)&out[2*d] = f22h(r0, r1);
    }
}

// -------------------- pixel-path attention: tensor-core fused (fp16) --------------------
__global__ void __launch_bounds__(256) pix_attn_tc(
        const __half* __restrict__ pqkvH, const __half* __restrict__ mqkvH,
        const float* __restrict__ bn_sim, const float* __restrict__ bn_ret,
        __half* __restrict__ pretH) {
    const int lt = blockIdx.x, h = blockIdx.y, b = blockIdx.z;
    const int tid = threadIdx.x;
    const int w = tid >> 5, lane = tid & 31;
    const int ly = lane >> 2, lx = lane & 3;

    __shared__ __half sKV[128 * 64];
    const uint32_t sKVu = smem_u32(sKV);

    stage_kv(sKV, mqkvH + (size_t)b * 128 * 512, h, tid);

    const int q0 = lt * 128 + w * 16;
    uint32_t aq[4];
    load_q(aq, pqkvH + (size_t)b * 4096 * 512, q0, h, lane);
    const float gs = bn_sim[h] * INV_C;
    const float gb = bn_sim[8 + h];
    __syncthreads();

    float S[16][4];
    #pragma unroll
    for (int nt = 0; nt < 16; nt++)
        S[nt][0] = S[nt][1] = S[nt][2] = S[nt][3] = 0.0f;
    qk_mma(S, aq, sKVu, lane);

    #pragma unroll
    for (int nt = 0; nt < 16; nt++)
        #pragma unroll
        for (int j = 0; j < 4; j++) {
            float x = fmaf(S[nt][j], gs, gb);
            S[nt][j] = rcpa(1.0f + ex2a(-x * L2E));
        }

    float O[4][4];
    #pragma unroll
    for (int i = 0; i < 4; i++) O[i][0] = O[i][1] = O[i][2] = O[i][3] = 0.0f;
    pv_mma(O, S, sKVu, lane);

    #pragma unroll
    for (int nt = 0; nt < 4; nt++) {
        const int d = nt * 8 + 2 * lx;
        const float g0 = bn_ret[h * 32 + d] * INV_C;
        const float g1 = bn_ret[h * 32 + d + 1] * INV_C;
        const float c0 = bn_ret[256 + h * 32 + d];
        const float c1 = bn_ret[256 + h * 32 + d + 1];
        const int l0 = q0 + ly, l1 = q0 + ly + 8;
        float v0 = fmaxf(fmaf(O[nt][0], g0, c0), 0.0f);
        float v1 = fmaxf(fmaf(O[nt][1], g1, c1), 0.0f);
        float v2 = fmaxf(fmaf(O[nt][2], g0, c0), 0.0f);
        float v3 = fmaxf(fmaf(O[nt][3], g1, c1), 0.0f);
        *(uint32_t*)&pretH[(size_t)(b * 4096 + l0) * 256 + h * 32 + d] = f22h(v0, v1);
        *(uint32_t*)&pretH[(size_t)(b * 4096 + l1) * 256 + h * 32 + d] = f22h(v2, v3);
    }
}

// -------------------- launch --------------------
#define NILP nullptr, nullptr, nullptr, nullptr, nullptr, 0

extern "C" void kernel_launch(void* const* d_in, const int* in_sizes, int n_in,
                              void* d_out, int out_size) {
    const float* pixel_input  = (const float*)d_in[0];
    const float* memory_input = (const float*)d_in[1];
    const float* W_mem1     = (const float*)d_in[2];
    const float* bn_mem1    = (const float*)d_in[3];
    const float* W_pix1     = (const float*)d_in[4];
    const float* bn_pix1    = (const float*)d_in[5];
    const float* W_mem_qkv  = (const float*)d_in[6];
    const float* bn_mem_qkv = (const float*)d_in[7];
    const float* W_pix_qkv  = (const float*)d_in[8];
    const float* bn_pix_qkv = (const float*)d_in[9];
    const float* bn_mem_sim = (const float*)d_in[10];
    const float* bn_mem_ret = (const float*)d_in[11];
    const float* bn_pix_sim = (const float*)d_in[12];
    const float* bn_pix_ret = (const float*)d_in[13];
    const float* W_mem3     = (const float*)d_in[14];
    const float* bn_mem3    = (const float*)d_in[15];
    const float* W_pix3     = (const float*)d_in[16];
    const float* bn_pix3    = (const float*)d_in[17];
    const float* W_ffn1     = (const float*)d_in[18];
    const float* bn_ffn1    = (const float*)d_in[19];
    const float* W_ffn2     = (const float*)d_in[20];
    const float* bn_ffn2    = (const float*)d_in[21];

    float* out_pix = (float*)d_out;
    float* out_mem = (float*)d_out + (size_t)MPIX * F_;

    __half *pixinH, *meminH, *pixH, *memH, *pqkvH, *mqkvH, *retmemH, *memoutH, *ffnH, *pretH, *wth;
    float *memout, *mpart, *skp;
    cudaGetSymbolAddress((void**)&pixinH,  g_pixinH);
    cudaGetSymbolAddress((void**)&meminH,  g_meminH);
    cudaGetSymbolAddress((void**)&pixH,    g_pixH);
    cudaGetSymbolAddress((void**)&pqkvH,   g_pqkvH);
    cudaGetSymbolAddress((void**)&memH,    g_memH);
    cudaGetSymbolAddress((void**)&mqkvH,   g_mqkvH);
    cudaGetSymbolAddress((void**)&retmemH, g_retmemH);
    cudaGetSymbolAddress((void**)&memout,  g_memout);
    cudaGetSymbolAddress((void**)&memoutH, g_memoutH);
    cudaGetSymbolAddress((void**)&ffnH,    g_ffnH);
    cudaGetSymbolAddress((void**)&pretH,   g_pretH);
    cudaGetSymbolAddress((void**)&mpart,   g_mpart);
    cudaGetSymbolAddress((void**)&wth,     g_wth);
    cudaGetSymbolAddress((void**)&skp,     g_skpart);

    cudaFuncSetAttribute(gemm_h<true,false,false,1,true>,  cudaFuncAttributeMaxDynamicSharedMemorySize, GEMM_SMEM);
    cudaFuncSetAttribute(gemm_h<false,false,false,1,true>, cudaFuncAttributeMaxDynamicSharedMemorySize, GEMM_SMEM);
    cudaFuncSetAttribute(gemm_h<true,true,false,2,false>,  cudaFuncAttributeMaxDynamicSharedMemorySize, GEMM_SMEM);
    cudaFuncSetAttribute(gemm_h<true,false,false,1,false>, cudaFuncAttributeMaxDynamicSharedMemorySize, GEMM_SMEM);
    cudaFuncSetAttribute(gemm_h<false,false,true,0,false>, cudaFuncAttributeMaxDynamicSharedMemorySize, GEMM_SMEM);
    cudaFuncSetAttribute(gemm_h<true,true,false,0,false>,  cudaFuncAttributeMaxDynamicSharedMemorySize, GEMM_SMEM);

    // prep: input conversions + weight transposes, one launch
    WTargs wa;
    wa.d[0] = {W_pix1,    wth + O_PIX1, F_,   BOT_, (BOT_/32)*(F_/32)};
    wa.d[1] = {W_mem1,    wth + O_MEM1, F_,   BOT_, (BOT_/32)*(F_/32)};
    wa.d[2] = {W_pix_qkv, wth + O_PQKV, BOT_, 512,  (512/32)*(BOT_/32)};
    wa.d[3] = {W_mem_qkv, wth + O_MQKV, BOT_, 512,  (512/32)*(BOT_/32)};
    wa.d[4] = {W_mem3,    wth + O_MEM3, TV_,  F_,   (F_/32)*(TV_/32)};
    wa.d[5] = {W_pix3,    wth + O_PIX3, TV_,  F_,   (F_/32)*(TV_/32)};
    wa.d[6] = {W_ffn1,    wth + O_FFN1, F_,   FFN_, (FFN_/32)*(F_/32)};
    wa.d[7] = {W_ffn2,    wth + O_FFN2, FFN_, F_,   (F_/32)*(FFN_/32)};
    const int ncvt = (MPIX*F_ + MMEM*F_) / 1024;  // 4224
    prep_all<<<ncvt + 896, 256>>>(wa, pixel_input, pixinH, MPIX*F_, memory_input, meminH, ncvt);

    // stage 1: pix1 + mem1 merged (out fp16)
    gemm_h<true,false,false,1,true><<<dim3(2, 264), 256, GEMM_SMEM>>>(
        pixinH, wth + O_PIX1, bn_pix1, nullptr, nullptr, pixH, MPIX, BOT_, F_, F_,
        meminH, wth + O_MEM1, bn_mem1, nullptr, memH, 256);
    // stage 2: pqkv + mqkv merged (out fp16)
    gemm_h<false,false,false,1,true><<<dim3(4, 264), 256, GEMM_SMEM>>>(
        pixH, wth + O_PQKV, bn_pix_qkv, nullptr, nullptr, pqkvH, MPIX, 512, BOT_, BOT_,
        memH, wth + O_MQKV, bn_mem_qkv, nullptr, mqkvH, 256);

    // fork: memory path on side stream, pixel path on main stream
    cudaEventRecord(g_fork.evF, 0);
    cudaStreamWaitEvent(g_fork.s2, g_fork.evF, 0);

    // ---- memory path (stream s2) ----
    mem_attn_split_tc<<<dim3(NSPLIT, H_, B_), 256, 0, g_fork.s2>>>(pqkvH, mqkvH, bn_mem_sim, mpart);
    mem_attn_combine<<<B_ * H_, 128, 0, g_fork.s2>>>(mpart, bn_mem_ret, retmemH);
    gemm_h<true,true,false,2,false><<<dim3(1, 8), 256, GEMM_SMEM, g_fork.s2>>>(
        retmemH, wth + O_MEM3, bn_mem3, memory_input, memout, memoutH, MMEM, F_, TV_, TV_, NILP);
    gemm_h<true,false,false,1,false><<<dim3(16, 8), 256, GEMM_SMEM, g_fork.s2>>>(
        memoutH, wth + O_FFN1, bn_ffn1, nullptr, nullptr, ffnH, MMEM, FFN_, F_, F_, NILP);
    gemm_h<false,false,true,0,false><<<dim3(1, 8, 8), 256, GEMM_SMEM, g_fork.s2>>>(
        ffnH, wth + O_FFN2, nullptr, nullptr, skp, nullptr, MMEM, F_, FFN_/8, FFN_, NILP);
    sk_reduce<<<(MMEM*F_)/256, 256, 0, g_fork.s2>>>(skp, bn_ffn2, memout, out_mem, MMEM, 8);

    // ---- pixel path (main stream) ----
    pix_attn_tc<<<dim3(L_/128, H_, B_), 256>>>(pqkvH, mqkvH, bn_pix_sim, bn_pix_ret, pretH);
    gemm_h<true,true,false,0,false><<<dim3(1, 256), 256, GEMM_SMEM>>>(
        pretH, wth + O_PIX3, bn_pix3, pixel_input, out_pix, nullptr, MPIX, F_, TV_, TV_, NILP);

    // join
    cudaEventRecord(g_fork.evJ, g_fork.s2);
    cudaStreamWaitEvent(0, g_fork.evJ, 0);
}

// round 16
// speedup vs baseline: 1.0474x; 1.0474x over previous
#include <cuda_runtime.h>
#include <cuda_fp16.h>
#include <cstdint>

// Problem constants
#define B_  8
#define L_  4096
#define N_  128
#define F_  128
#define H_  8
#define TV_ 256
#define BOT_ 256
#define FFN_ 2048
#define INV_C 0.9995003746877732f  // 1/sqrt(1+1e-3)
#define L2E  1.4426950408889634f

#define MPIX (B_*L_)   // 32768
#define MMEM (B_*N_)   // 1024
#define NSPLIT 9       // 8 pixel-key splits + 1 mem-key split

// -------------------- scratch (device globals; no allocation) --------------------
__device__ __half g_pixinH[MPIX*F_];
__device__ __half g_meminH[MMEM*F_];
__device__ __half g_pixH [MPIX*BOT_];
__device__ __half g_pqkvH[(size_t)MPIX*512];
__device__ __half g_memH [MMEM*BOT_];
__device__ __half g_mqkvH[MMEM*512];
__device__ __half g_retmemH[MMEM*TV_];
__device__ float  g_memout[MMEM*F_];
__device__ __half g_memoutH[MMEM*F_];
__device__ __half g_ffnH [MMEM*FFN_];
__device__ __half g_pretH[(size_t)MPIX*TV_];
__device__ float  g_mpart[64*NSPLIT*34*128];
__device__ __half g_wth[917504];        // transposed fp16 weights
__device__ float  g_skpart[8*MMEM*F_];  // split-K partials for ffn2

// offsets into g_wth
#define O_PIX1 0
#define O_MEM1 32768
#define O_PQKV 65536
#define O_MQKV 196608
#define O_MEM3 327680
#define O_PIX3 360448
#define O_FFN1 393216
#define O_FFN2 655360

// -------------------- streams/events for capture fork-join --------------------
struct ForkCtx {
    cudaStream_t s2;
    cudaEvent_t evF, evJ;
    ForkCtx() {
        cudaStreamCreate(&s2);
        cudaEventCreateWithFlags(&evF, cudaEventDisableTiming);
        cudaEventCreateWithFlags(&evJ, cudaEventDisableTiming);
    }
};
static ForkCtx g_fork;

// -------------------- fast math --------------------
__device__ __forceinline__ float ex2a(float x){ float r; asm("ex2.approx.f32 %0, %1;" : "=f"(r):"f"(x)); return r; }
__device__ __forceinline__ float rcpa(float x){ float r; asm("rcp.approx.f32 %0, %1;" : "=f"(r):"f"(x)); return r; }
__device__ __forceinline__ uint32_t f22h(float a, float b){
    uint32_t r;
    asm("cvt.rn.f16x2.f32 %0, %1, %2;" : "=r"(r) : "f"(b), "f"(a));
    return r;
}
__device__ __forceinline__ uint32_t smem_u32(const void* p){
    uint32_t a; asm("{ .reg .u64 t; cvta.to.shared.u64 t, %1; cvt.u32.u64 %0, t; }" : "=r"(a) : "l"(p));
    return a;
}
__device__ __forceinline__ void cpa16(uint32_t s, const void* g){
    asm volatile("cp.async.ca.shared.global [%0], [%1], 16;" :: "r"(s), "l"(g));
}
#define CP_COMMIT() asm volatile("cp.async.commit_group;" ::: "memory")

__device__ __forceinline__ void ldsm4(uint32_t* r, uint32_t addr){
    asm volatile("ldmatrix.sync.aligned.m8n8.x4.shared.b16 {%0,%1,%2,%3}, [%4];"
        : "=r"(r[0]), "=r"(r[1]), "=r"(r[2]), "=r"(r[3]) : "r"(addr));
}
__device__ __forceinline__ void ldsm4t(uint32_t* r, uint32_t addr){
    asm volatile("ldmatrix.sync.aligned.m8n8.x4.trans.shared.b16 {%0,%1,%2,%3}, [%4];"
        : "=r"(r[0]), "=r"(r[1]), "=r"(r[2]), "=r"(r[3]) : "r"(addr));
}

// fp16 mma: D[16x8] += A[16x16] * B[16x8]
__device__ __forceinline__ void mma16(float* d, const uint32_t* a, uint32_t b0, uint32_t b1){
    asm volatile("mma.sync.aligned.m16n8k16.row.col.f32.f16.f16.f32 "
        "{%0,%1,%2,%3}, {%4,%5,%6,%7}, {%8,%9}, {%0,%1,%2,%3};"
        : "+f"(d[0]), "+f"(d[1]), "+f"(d[2]), "+f"(d[3])
        : "r"(a[0]), "r"(a[1]), "r"(a[2]), "r"(a[3]), "r"(b0), "r"(b1));
}

// -------------------- prep: input cvt + weight transpose, one launch --------------------
struct WTd { const float* in; __half* out; int K; int N; int tiles; };
struct WTargs { WTd d[8]; };

__global__ void __launch_bounds__(256) prep_all(
        WTargs a,
        const float* __restrict__ pin, __half* __restrict__ pinH, int na,
        const float* __restrict__ min_, __half* __restrict__ minH, int ncvt) {
    __shared__ float t[32][33];
    if ((int)blockIdx.x < ncvt) {
        const int q = (blockIdx.x * 256 + threadIdx.x) * 4;
        if (q < na) {
            float4 v = *(const float4*)(pin + q);
            uint2 u = {f22h(v.x, v.y), f22h(v.z, v.w)};
            *(uint2*)(pinH + q) = u;
        } else {
            const int p = q - na;
            float4 v = *(const float4*)(min_ + p);
            uint2 u = {f22h(v.x, v.y), f22h(v.z, v.w)};
            *(uint2*)(minH + p) = u;
        }
        return;
    }
    int tile = blockIdx.x - ncvt;
    int i = 0;
    while (i < 7 && tile >= a.d[i].tiles) { tile -= a.d[i].tiles; i++; }
    const float* in = a.d[i].in;
    __half* out = a.d[i].out;
    const int K = a.d[i].K, Nn = a.d[i].N;
    const int ntx = Nn >> 5;
    const int bx = tile % ntx, by = tile / ntx;
    const int tx = threadIdx.x & 31, ty = threadIdx.x >> 5;
    #pragma unroll
    for (int j = 0; j < 4; j++)
        t[ty + j * 8][tx] = in[(size_t)(by * 32 + ty + j * 8) * Nn + bx * 32 + tx];
    __syncthreads();
    #pragma unroll
    for (int j = 0; j < 4; j++)
        out[(size_t)(bx * 32 + ty + j * 8) * K + by * 32 + tx] = __float2half_rn(t[tx][ty + j * 8]);
}

// -------------------- fp16 mma GEMM: cp.async + ldmatrix --------------------
template<bool RELU, bool RES, bool PARTIAL, int OH, bool DUAL>
__global__ void __launch_bounds__(256, 2) gemm_h(
        const __half* __restrict__ A, const __half* __restrict__ Bt,
        const float* __restrict__ bn, const float* __restrict__ res,
        float* __restrict__ C, __half* __restrict__ Ch, int M, int Nn, int K, int lda,
        const __half* __restrict__ A2, const __half* __restrict__ Bt2,
        const float* __restrict__ bn2, float* __restrict__ C2, __half* __restrict__ Ch2,
        int ysplit) {
    extern __shared__ __half smh[];
    float* bns = (float*)(smh + 32768);
    const uint32_t sAu = smem_u32(smh);
    const uint32_t sBu = sAu + 32768;
    const int tid = threadIdx.x;
    const int w = tid >> 5, lane = tid & 31;
    const int lx = lane & 3;
    const int wm = w >> 2, wn = w & 3;
    const int n0 = blockIdx.x * 128;

    const __half* Abase = A;
    const __half* Btb = Bt;
    const float* bnp = bn;
    float* Cp_ = C;
    __half* Chp = Ch;
    int by = blockIdx.y;
    if (DUAL && by >= ysplit) {
        by -= ysplit;
        Abase = A2; Btb = Bt2; bnp = bn2; Cp_ = C2; Chp = Ch2;
    }
    const int m0 = by * 128;
    const int kbeg = PARTIAL ? blockIdx.z * K : 0;

    if (!PARTIAL && tid < 128) {
        bns[tid]       = bnp[n0 + tid] * INV_C;
        bns[128 + tid] = bnp[Nn + n0 + tid];
    }

    const int r = tid >> 1, hh = tid & 1;
    const __half* Ap = Abase + (size_t)(m0 + r) * lda + kbeg + hh * 32;
    const __half* Bp = Btb + (size_t)(n0 + r) * lda + kbeg + hh * 32;
    uint32_t stA[4], stB[4];
    #pragma unroll
    for (int j = 0; j < 4; j++) {
        const uint32_t u = (uint32_t)(((hh * 4 + j) ^ (r & 7)) << 3);
        stA[j] = sAu + (uint32_t)(r * 64 + u) * 2;
        stB[j] = sBu + (uint32_t)(r * 64 + u) * 2;
    }

    const int sub = lane >> 3;
    const int a_ro = (sub & 1) * 8 + (lane & 7);
    const int a_c  = sub >> 1;
    const int b_ro = (sub >> 1) * 8 + (lane & 7);
    const int b_c  = sub & 1;
    uint32_t rowA_b[4]; int rpA[4];
    #pragma unroll
    for (int mt = 0; mt < 4; mt++) {
        const int row = wm * 64 + mt * 16 + a_ro;
        rowA_b[mt] = (uint32_t)row * 128;
        rpA[mt] = row & 7;
    }
    uint32_t rowB_b[2]; int rpB[2];
    #pragma unroll
    for (int p = 0; p < 2; p++) {
        const int n = wn * 32 + p * 16 + b_ro;
        rowB_b[p] = (uint32_t)n * 128;
        rpB[p] = n & 7;
    }

    const int KB = K >> 6;
    #pragma unroll
    for (int j = 0; j < 4; j++) {
        cpa16(stA[j], Ap + j * 8);
        cpa16(stB[j], Bp + j * 8);
    }
    CP_COMMIT();

    float acc[4][4][4];
    #pragma unroll
    for (int a = 0; a < 4; a++)
        #pragma unroll
        for (int b = 0; b < 4; b++)
            #pragma unroll
            for (int c = 0; c < 4; c++) acc[a][b][c] = 0.0f;

    for (int kb = 0; kb < KB; kb++) {
        if (kb + 1 < KB) {
            const uint32_t bo = (uint32_t)(((kb + 1) & 1) * 16384);
            #pragma unroll
            for (int j = 0; j < 4; j++) {
                cpa16(stA[j] + bo, Ap + (size_t)(kb + 1) * 64 + j * 8);
                cpa16(stB[j] + bo, Bp + (size_t)(kb + 1) * 64 + j * 8);
            }
            CP_COMMIT();
            asm volatile("cp.async.wait_group 1;" ::: "memory");
        } else {
            asm volatile("cp.async.wait_group 0;" ::: "memory");
        }
        __syncthreads();

        const uint32_t bufA = sAu + (uint32_t)((kb & 1) * 16384);
        const uint32_t bufB = sBu + (uint32_t)((kb & 1) * 16384);
        #pragma unroll
        for (int kt = 0; kt < 4; kt++) {
            const int ub = 2 * kt;
            uint32_t af[4][4], bf[4][2];
            #pragma unroll
            for (int p = 0; p < 2; p++) {
                uint32_t rr[4];
                ldsm4(rr, bufB + rowB_b[p] + (uint32_t)(((ub + b_c) ^ rpB[p]) << 4));
                bf[2*p][0]   = rr[0]; bf[2*p][1]   = rr[1];
                bf[2*p+1][0] = rr[2]; bf[2*p+1][1] = rr[3];
            }
            #pragma unroll
            for (int mt = 0; mt < 4; mt++)
                ldsm4(af[mt], bufA + rowA_b[mt] + (uint32_t)(((ub + a_c) ^ rpA[mt]) << 4));
            #pragma unroll
            for (int mt = 0; mt < 4; mt++)
                #pragma unroll
                for (int nt = 0; nt < 4; nt++)
                    mma16(acc[mt][nt], af[mt], bf[nt][0], bf[nt][1]);
        }
        __syncthreads();
    }

    const int ly = lane >> 2;
    if (PARTIAL) {
        float* Cpz = Cp_ + (size_t)blockIdx.z * M * Nn;
        #pragma unroll
        for (int mt = 0; mt < 4; mt++) {
            const int rr = m0 + wm * 64 + mt * 16 + ly;
            #pragma unroll
            for (int nt = 0; nt < 4; nt++) {
                const int cc = n0 + wn * 32 + nt * 8 + lx * 2;
                float2 v0 = {acc[mt][nt][0], acc[mt][nt][1]};
                float2 v1 = {acc[mt][nt][2], acc[mt][nt][3]};
                *(float2*)&Cpz[(size_t)rr * Nn + cc] = v0;
                *(float2*)&Cpz[(size_t)(rr + 8) * Nn + cc] = v1;
            }
        }
    } else {
        #pragma unroll
        for (int mt = 0; mt < 4; mt++) {
            const int rr = m0 + wm * 64 + mt * 16 + ly;
            #pragma unroll
            for (int nt = 0; nt < 4; nt++) {
                const int lc = wn * 32 + nt * 8 + lx * 2;
                const int cc = n0 + lc;
                const float g0 = bns[lc], g1 = bns[lc + 1];
                const float b0 = bns[128 + lc], b1 = bns[128 + lc + 1];
                float2 v0, v1;
                v0.x = fmaf(acc[mt][nt][0], g0, b0);
                v0.y = fmaf(acc[mt][nt][1], g1, b1);
                v1.x = fmaf(acc[mt][nt][2], g0, b0);
                v1.y = fmaf(acc[mt][nt][3], g1, b1);
                const size_t i0 = (size_t)rr * Nn + cc;
                const size_t i1 = (size_t)(rr + 8) * Nn + cc;
                if (RES) {
                    float2 r0 = *(const float2*)&res[i0];
                    float2 r1 = *(const float2*)&res[i1];
                    v0.x += r0.x; v0.y += r0.y; v1.x += r1.x; v1.y += r1.y;
                }
                if (RELU) {
                    v0.x = fmaxf(v0.x, 0.0f); v0.y = fmaxf(v0.y, 0.0f);
                    v1.x = fmaxf(v1.x, 0.0f); v1.y = fmaxf(v1.y, 0.0f);
                }
                if (OH == 0 || OH == 2) {
                    *(float2*)&Cp_[i0] = v0;
                    *(float2*)&Cp_[i1] = v1;
                }
                if (OH >= 1) {
                    *(uint32_t*)&Chp[i0] = f22h(v0.x, v0.y);
                    *(uint32_t*)&Chp[i1] = f22h(v1.x, v1.y);
                }
            }
        }
    }
}

#define GEMM_SMEM (65536 + 1024)

// split-K reduce for ffn2
__global__ void __launch_bounds__(256) sk_reduce(
        const float* __restrict__ part, const float* __restrict__ bn,
        const float* __restrict__ res, float* __restrict__ out, int M, int SK) {
    const int idx = blockIdx.x * 256 + threadIdx.x;
    const int c = idx & 127;
    float s = 0.0f;
    for (int k = 0; k < SK; k++) s += part[(size_t)k * M * 128 + idx];
    float v = fmaf(s, bn[c] * INV_C, bn[128 + c]) + res[idx];
    out[idx] = fmaxf(v, 0.0f);
}

// ==================== shared attention helpers (fp16 KV tile) ====================
// sKV layout: 128 key rows x 64 halves (128B), 16B-unit XOR swizzle u^(row&7).
// units 0-1: K dims 0..15; units 2-5: V dims 0..31.

__device__ __forceinline__ void stage_kv(__half* sKV, const __half* kvbase, int h, int tid){
    const int row = tid >> 1, part = tid & 1;
    const __half* src = kvbase + (size_t)row * 512;
    char* dst = (char*)sKV + row * 128;
    if (part == 0) {
        uint4 k0 = *(const uint4*)(src + 128 + h * 16);
        uint4 k1 = *(const uint4*)(src + 128 + h * 16 + 8);
        uint4 v0 = *(const uint4*)(src + 256 + h * 32);
        *(uint4*)(dst + (((0 ^ (row & 7))) << 4)) = k0;
        *(uint4*)(dst + (((1 ^ (row & 7))) << 4)) = k1;
        *(uint4*)(dst + (((2 ^ (row & 7))) << 4)) = v0;
    } else {
        uint4 v1 = *(const uint4*)(src + 256 + h * 32 + 8);
        uint4 v2 = *(const uint4*)(src + 256 + h * 32 + 16);
        uint4 v3 = *(const uint4*)(src + 256 + h * 32 + 24);
        *(uint4*)(dst + (((3 ^ (row & 7))) << 4)) = v1;
        *(uint4*)(dst + (((4 ^ (row & 7))) << 4)) = v2;
        *(uint4*)(dst + (((5 ^ (row & 7))) << 4)) = v3;
    }
}

__device__ __forceinline__ void load_q(uint32_t* aq, const __half* qbase, int q0, int h, int lane){
    const int ly = lane >> 2, lx = lane & 3;
    const __half* r0 = qbase + (size_t)(q0 + ly) * 512 + h * 16;
    const __half* r1 = r0 + (size_t)8 * 512;
    aq[0] = *(const uint32_t*)(r0 + 2 * lx);
    aq[1] = *(const uint32_t*)(r1 + 2 * lx);
    aq[2] = *(const uint32_t*)(r0 + 2 * lx + 8);
    aq[3] = *(const uint32_t*)(r1 + 2 * lx + 8);
}

__device__ __forceinline__ void qk_mma(float (*S)[4], const uint32_t* aq, uint32_t sKVu, int lane){
    const int key_off = ((lane >> 4) << 3) + (lane & 7);
    const int unit = (lane >> 3) & 1;
    #pragma unroll
    for (int p = 0; p < 8; p++) {
        const int key = p * 16 + key_off;
        uint32_t rr[4];
        ldsm4(rr, sKVu + (uint32_t)key * 128 + (uint32_t)((unit ^ (key & 7)) << 4));
        mma16(S[2*p],   aq, rr[0], rr[1]);
        mma16(S[2*p+1], aq, rr[2], rr[3]);
    }
}

__device__ __forceinline__ void pv_mma(float (*O)[4], const float (*S)[4], uint32_t sKVu, int lane){
    const int key_off = ((lane >> 3) & 1) * 8 + (lane & 7);
    const int ug = lane >> 4;  // 0/1
    #pragma unroll
    for (int j = 0; j < 8; j++) {
        uint32_t as[4];
        as[0] = f22h(S[2*j][0],   S[2*j][1]);
        as[1] = f22h(S[2*j][2],   S[2*j][3]);
        as[2] = f22h(S[2*j+1][0], S[2*j+1][1]);
        as[3] = f22h(S[2*j+1][2], S[2*j+1][3]);
        const int key = j * 16 + key_off;
        uint32_t rr[4];
        const int u0 = 2 + ug;
        ldsm4t(rr, sKVu + (uint32_t)key * 128 + (uint32_t)((u0 ^ (key & 7)) << 4));
        mma16(O[0], as, rr[0], rr[1]);
        mma16(O[1], as, rr[2], rr[3]);
        const int u1 = 4 + ug;
        ldsm4t(rr, sKVu + (uint32_t)key * 128 + (uint32_t)((u1 ^ (key & 7)) << 4));
        mma16(O[2], as, rr[0], rr[1]);
        mma16(O[3], as, rr[2], rr[3]);
    }
}

// -------------------- memory-path attention: tensor-core flash split (fp16) -----------
__global__ void __launch_bounds__(256, 2) mem_attn_split_tc(
        const __half* __restrict__ pqkvH, const __half* __restrict__ mqkvH,
        const float* __restrict__ bn_sim, float* __restrict__ part) {
    const int s = blockIdx.x, h = blockIdx.y, b = blockIdx.z;
    const int tid = threadIdx.x;
    const int w = tid >> 5, lane = tid & 31;
    const int ly = lane >> 2, lx = lane & 3;

    __shared__ __half sKV[128 * 64];
    const uint32_t sKVu = smem_u32(sKV);

    const int q0 = w * 16;
    uint32_t aq[4];
    load_q(aq, mqkvH + (size_t)b * 128 * 512, q0, h, lane);
    const float gs = bn_sim[h] * INV_C;
    const float gb = bn_sim[8 + h];

    float m0 = -1e30f, m1 = -1e30f, li0 = 0.0f, li1 = 0.0f;
    float O[4][4];
    #pragma unroll
    for (int i = 0; i < 4; i++) O[i][0] = O[i][1] = O[i][2] = O[i][3] = 0.0f;

    const int ntiles = (s < 8) ? 4 : 1;
    for (int t = 0; t < ntiles; t++) {
        const __half* kvbase = (s < 8)
            ? pqkvH + (size_t)(b * 4096 + s * 512 + t * 128) * 512
            : mqkvH + (size_t)(b * 128) * 512;
        stage_kv(sKV, kvbase, h, tid);
        __syncthreads();

        float S[16][4];
        #pragma unroll
        for (int nt = 0; nt < 16; nt++)
            S[nt][0] = S[nt][1] = S[nt][2] = S[nt][3] = 0.0f;
        qk_mma(S, aq, sKVu, lane);

        float lm0 = -1e30f, lm1 = -1e30f;
        #pragma unroll
        for (int nt = 0; nt < 16; nt++) {
            S[nt][0] = fmaf(S[nt][0], gs, gb);
            S[nt][1] = fmaf(S[nt][1], gs, gb);
            S[nt][2] = fmaf(S[nt][2], gs, gb);
            S[nt][3] = fmaf(S[nt][3], gs, gb);
            lm0 = fmaxf(lm0, fmaxf(S[nt][0], S[nt][1]));
            lm1 = fmaxf(lm1, fmaxf(S[nt][2], S[nt][3]));
        }
        lm0 = fmaxf(lm0, __shfl_xor_sync(0xffffffffu, lm0, 1));
        lm0 = fmaxf(lm0, __shfl_xor_sync(0xffffffffu, lm0, 2));
        lm1 = fmaxf(lm1, __shfl_xor_sync(0xffffffffu, lm1, 1));
        lm1 = fmaxf(lm1, __shfl_xor_sync(0xffffffffu, lm1, 2));
        const float nm0 = fmaxf(m0, lm0), nm1 = fmaxf(m1, lm1);
        const float c0 = ex2a((m0 - nm0) * L2E);
        const float c1 = ex2a((m1 - nm1) * L2E);
        m0 = nm0; m1 = nm1;
        li0 *= c0; li1 *= c1;
        #pragma unroll
        for (int nt = 0; nt < 4; nt++) {
            O[nt][0] *= c0; O[nt][1] *= c0;
            O[nt][2] *= c1; O[nt][3] *= c1;
        }
        #pragma unroll
        for (int nt = 0; nt < 16; nt++) {
            S[nt][0] = ex2a((S[nt][0] - nm0) * L2E);
            S[nt][1] = ex2a((S[nt][1] - nm0) * L2E);
            S[nt][2] = ex2a((S[nt][2] - nm1) * L2E);
            S[nt][3] = ex2a((S[nt][3] - nm1) * L2E);
            li0 += S[nt][0] + S[nt][1];
            li1 += S[nt][2] + S[nt][3];
        }
        pv_mma(O, S, sKVu, lane);
        __syncthreads();
    }

    li0 += __shfl_xor_sync(0xffffffffu, li0, 1);
    li0 += __shfl_xor_sync(0xffffffffu, li0, 2);
    li1 += __shfl_xor_sync(0xffffffffu, li1, 1);
    li1 += __shfl_xor_sync(0xffffffffu, li1, 2);

    float* base = part + (size_t)(((b * 8 + h) * NSPLIT + s) * 34) * 128;
    const int r0 = q0 + ly, r1 = q0 + ly + 8;
    if (lx == 0) {
        base[r0] = m0;        base[r1] = m1;
        base[128 + r0] = li0; base[128 + r1] = li1;
    }
    #pragma unroll
    for (int nt = 0; nt < 4; nt++) {
        const int c = nt * 8 + 2 * lx;
        base[(2 + c)     * 128 + r0] = O[nt][0];
        base[(2 + c + 1) * 128 + r0] = O[nt][1];
        base[(2 + c)     * 128 + r1] = O[nt][2];
        base[(2 + c + 1) * 128 + r1] = O[nt][3];
    }
}

// combine: outputs fp16 retmem
__global__ void __launch_bounds__(128) mem_attn_combine(
        const float* __restrict__ part, const float* __restrict__ bn_ret,
        __half* __restrict__ retmemH) {
    const int bh = blockIdx.x;
    const int n = threadIdx.x;
    const int b = bh >> 3, h = bh & 7;
    float M = -1e30f;
    #pragma unroll
    for (int s = 0; s < NSPLIT; s++)
        M = fmaxf(M, part[(size_t)((bh * NSPLIT + s) * 34) * 128 + n]);
    float Lsum = 0.0f;
    float acc[32] = {};
    #pragma unroll
    for (int s = 0; s < NSPLIT; s++) {
        const float* base = part + (size_t)((bh * NSPLIT + s) * 34) * 128;
        float wgt = ex2a((base[n] - M) * L2E);
        Lsum = fmaf(base[128 + n], wgt, Lsum);
        #pragma unroll
        for (int d = 0; d < 32; d++)
            acc[d] = fmaf(wgt, base[(2 + d) * 128 + n], acc[d]);
    }
    float inv = rcpa(Lsum);
    inv = inv * (2.0f - Lsum * inv);
    __half* out = retmemH + (size_t)(b * 128 + n) * 256 + h * 32;
    #pragma unroll
    for (int d = 0; d < 16; d++) {
        float r0 = acc[2*d]   * inv;
        float r1 = acc[2*d+1] * inv;
        r0 = fmaxf(fmaf(r0, bn_ret[h * 32 + 2*d]   * INV_C, bn_ret[256 + h * 32 + 2*d]),   0.0f);
        r1 = fmaxf(fmaf(r1, bn_ret[h * 32 + 2*d+1] * INV_C, bn_ret[256 + h * 32 + 2*d+1]), 0.0f);
        *(uint32_t*)&out[2*d] = f22h(r0, r1);
    }
}

// -------------------- pixel-path attention: tensor-core fused (fp16) --------------------
__global__ void __launch_bounds__(256, 2) pix_attn_tc(
        const __half* __restrict__ pqkvH, const __half* __restrict__ mqkvH,
        const float* __restrict__ bn_sim, const float* __restrict__ bn_ret,
        __half* __restrict__ pretH) {
    const int lt = blockIdx.x, h = blockIdx.y, b = blockIdx.z;
    const int tid = threadIdx.x;
    const int w = tid >> 5, lane = tid & 31;
    const int ly = lane >> 2, lx = lane & 3;

    __shared__ __half sKV[128 * 64];
    const uint32_t sKVu = smem_u32(sKV);

    stage_kv(sKV, mqkvH + (size_t)b * 128 * 512, h, tid);

    const int q0 = lt * 128 + w * 16;
    uint32_t aq[4];
    load_q(aq, pqkvH + (size_t)b * 4096 * 512, q0, h, lane);
    const float gs = bn_sim[h] * INV_C;
    const float gb = bn_sim[8 + h];
    __syncthreads();

    float S[16][4];
    #pragma unroll
    for (int nt = 0; nt < 16; nt++)
        S[nt][0] = S[nt][1] = S[nt][2] = S[nt][3] = 0.0f;
    qk_mma(S, aq, sKVu, lane);

    #pragma unroll
    for (int nt = 0; nt < 16; nt++)
        #pragma unroll
        for (int j = 0; j < 4; j++) {
            float x = fmaf(S[nt][j], gs, gb);
            S[nt][j] = rcpa(1.0f + ex2a(-x * L2E));
        }

    float O[4][4];
    #pragma unroll
    for (int i = 0; i < 4; i++) O[i][0] = O[i][1] = O[i][2] = O[i][3] = 0.0f;
    pv_mma(O, S, sKVu, lane);

    #pragma unroll
    for (int nt = 0; nt < 4; nt++) {
        const int d = nt * 8 + 2 * lx;
        const float g0 = bn_ret[h * 32 + d] * INV_C;
        const float g1 = bn_ret[h * 32 + d + 1] * INV_C;
        const float c0 = bn_ret[256 + h * 32 + d];
        const float c1 = bn_ret[256 + h * 32 + d + 1];
        const int l0 = q0 + ly, l1 = q0 + ly + 8;
        float v0 = fmaxf(fmaf(O[nt][0], g0, c0), 0.0f);
        float v1 = fmaxf(fmaf(O[nt][1], g1, c1), 0.0f);
        float v2 = fmaxf(fmaf(O[nt][2], g0, c0), 0.0f);
        float v3 = fmaxf(fmaf(O[nt][3], g1, c1), 0.0f);
        *(uint32_t*)&pretH[(size_t)(b * 4096 + l0) * 256 + h * 32 + d] = f22h(v0, v1);
        *(uint32_t*)&pretH[(size_t)(b * 4096 + l1) * 256 + h * 32 + d] = f22h(v2, v3);
    }
}

// -------------------- launch --------------------
#define NILP nullptr, nullptr, nullptr, nullptr, nullptr, 0

extern "C" void kernel_launch(void* const* d_in, const int* in_sizes, int n_in,
                              void* d_out, int out_size) {
    const float* pixel_input  = (const float*)d_in[0];
    const float* memory_input = (const float*)d_in[1];
    const float* W_mem1     = (const float*)d_in[2];
    const float* bn_mem1    = (const float*)d_in[3];
    const float* W_pix1     = (const float*)d_in[4];
    const float* bn_pix1    = (const float*)d_in[5];
    const float* W_mem_qkv  = (const float*)d_in[6];
    const float* bn_mem_qkv = (const float*)d_in[7];
    const float* W_pix_qkv  = (const float*)d_in[8];
    const float* bn_pix_qkv = (const float*)d_in[9];
    const float* bn_mem_sim = (const float*)d_in[10];
    const float* bn_mem_ret = (const float*)d_in[11];
    const float* bn_pix_sim = (const float*)d_in[12];
    const float* bn_pix_ret = (const float*)d_in[13];
    const float* W_mem3     = (const float*)d_in[14];
    const float* bn_mem3    = (const float*)d_in[15];
    const float* W_pix3     = (const float*)d_in[16];
    const float* bn_pix3    = (const float*)d_in[17];
    const float* W_ffn1     = (const float*)d_in[18];
    const float* bn_ffn1    = (const float*)d_in[19];
    const float* W_ffn2     = (const float*)d_in[20];
    const float* bn_ffn2    = (const float*)d_in[21];

    float* out_pix = (float*)d_out;
    float* out_mem = (float*)d_out + (size_t)MPIX * F_;

    __half *pixinH, *meminH, *pixH, *memH, *pqkvH, *mqkvH, *retmemH, *memoutH, *ffnH, *pretH, *wth;
    float *memout, *mpart, *skp;
    cudaGetSymbolAddress((void**)&pixinH,  g_pixinH);
    cudaGetSymbolAddress((void**)&meminH,  g_meminH);
    cudaGetSymbolAddress((void**)&pixH,    g_pixH);
    cudaGetSymbolAddress((void**)&pqkvH,   g_pqkvH);
    cudaGetSymbolAddress((void**)&memH,    g_memH);
    cudaGetSymbolAddress((void**)&mqkvH,   g_mqkvH);
    cudaGetSymbolAddress((void**)&retmemH, g_retmemH);
    cudaGetSymbolAddress((void**)&memout,  g_memout);
    cudaGetSymbolAddress((void**)&memoutH, g_memoutH);
    cudaGetSymbolAddress((void**)&ffnH,    g_ffnH);
    cudaGetSymbolAddress((void**)&pretH,   g_pretH);
    cudaGetSymbolAddress((void**)&mpart,   g_mpart);
    cudaGetSymbolAddress((void**)&wth,     g_wth);
    cudaGetSymbolAddress((void**)&skp,     g_skpart);

    cudaFuncSetAttribute(gemm_h<true,false,false,1,true>,  cudaFuncAttributeMaxDynamicSharedMemorySize, GEMM_SMEM);
    cudaFuncSetAttribute(gemm_h<false,false,false,1,true>, cudaFuncAttributeMaxDynamicSharedMemorySize, GEMM_SMEM);
    cudaFuncSetAttribute(gemm_h<true,true,false,2,false>,  cudaFuncAttributeMaxDynamicSharedMemorySize, GEMM_SMEM);
    cudaFuncSetAttribute(gemm_h<true,false,false,1,false>, cudaFuncAttributeMaxDynamicSharedMemorySize, GEMM_SMEM);
    cudaFuncSetAttribute(gemm_h<false,false,true,0,false>, cudaFuncAttributeMaxDynamicSharedMemorySize, GEMM_SMEM);
    cudaFuncSetAttribute(gemm_h<true,true,false,0,false>,  cudaFuncAttributeMaxDynamicSharedMemorySize, GEMM_SMEM);

    // prep: input conversions + weight transposes, one launch
    WTargs wa;
    wa.d[0] = {W_pix1,    wth + O_PIX1, F_,   BOT_, (BOT_/32)*(F_/32)};
    wa.d[1] = {W_mem1,    wth + O_MEM1, F_,   BOT_, (BOT_/32)*(F_/32)};
    wa.d[2] = {W_pix_qkv, wth + O_PQKV, BOT_, 512,  (512/32)*(BOT_/32)};
    wa.d[3] = {W_mem_qkv, wth + O_MQKV, BOT_, 512,  (512/32)*(BOT_/32)};
    wa.d[4] = {W_mem3,    wth + O_MEM3, TV_,  F_,   (F_/32)*(TV_/32)};
    wa.d[5] = {W_pix3,    wth + O_PIX3, TV_,  F_,   (F_/32)*(TV_/32)};
    wa.d[6] = {W_ffn1,    wth + O_FFN1, F_,   FFN_, (FFN_/32)*(F_/32)};
    wa.d[7] = {W_ffn2,    wth + O_FFN2, FFN_, F_,   (F_/32)*(FFN_/32)};
    const int ncvt = (MPIX*F_ + MMEM*F_) / 1024;  // 4224
    prep_all<<<ncvt + 896, 256>>>(wa, pixel_input, pixinH, MPIX*F_, memory_input, meminH, ncvt);

    // stage 1: pix1 + mem1 merged (out fp16)
    gemm_h<true,false,false,1,true><<<dim3(2, 264), 256, GEMM_SMEM>>>(
        pixinH, wth + O_PIX1, bn_pix1, nullptr, nullptr, pixH, MPIX, BOT_, F_, F_,
        meminH, wth + O_MEM1, bn_mem1, nullptr, memH, 256);
    // stage 2: pqkv + mqkv merged (out fp16)
    gemm_h<false,false,false,1,true><<<dim3(4, 264), 256, GEMM_SMEM>>>(
        pixH, wth + O_PQKV, bn_pix_qkv, nullptr, nullptr, pqkvH, MPIX, 512, BOT_, BOT_,
        memH, wth + O_MQKV, bn_mem_qkv, nullptr, mqkvH, 256);

    // fork: memory path on side stream, pixel path on main stream
    cudaEventRecord(g_fork.evF, 0);
    cudaStreamWaitEvent(g_fork.s2, g_fork.evF, 0);

    // ---- memory path (stream s2) ----
    mem_attn_split_tc<<<dim3(NSPLIT, H_, B_), 256, 0, g_fork.s2>>>(pqkvH, mqkvH, bn_mem_sim, mpart);
    mem_attn_combine<<<B_ * H_, 128, 0, g_fork.s2>>>(mpart, bn_mem_ret, retmemH);
    gemm_h<true,true,false,2,false><<<dim3(1, 8), 256, GEMM_SMEM, g_fork.s2>>>(
        retmemH, wth + O_MEM3, bn_mem3, memory_input, memout, memoutH, MMEM, F_, TV_, TV_, NILP);
    gemm_h<true,false,false,1,false><<<dim3(16, 8), 256, GEMM_SMEM, g_fork.s2>>>(
        memoutH, wth + O_FFN1, bn_ffn1, nullptr, nullptr, ffnH, MMEM, FFN_, F_, F_, NILP);
    gemm_h<false,false,true,0,false><<<dim3(1, 8, 8), 256, GEMM_SMEM, g_fork.s2>>>(
        ffnH, wth + O_FFN2, nullptr, nullptr, skp, nullptr, MMEM, F_, FFN_/8, FFN_, NILP);
    sk_reduce<<<(MMEM*F_)/256, 256, 0, g_fork.s2>>>(skp, bn_ffn2, memout, out_mem, MMEM, 8);

    // ---- pixel path (main stream) ----
    pix_attn_tc<<<dim3(L_/128, H_, B_), 256>>>(pqkvH, mqkvH, bn_pix_sim, bn_pix_ret, pretH);
    gemm_h<true,true,false,0,false><<<dim3(1, 256), 256, GEMM_SMEM>>>(
        pretH, wth + O_PIX3, bn_pix3, pixel_input, out_pix, nullptr, MPIX, F_, TV_, TV_, NILP);

    // join
    cudaEventRecord(g_fork.evJ, g_fork.s2);
    cudaStreamWaitEvent(0, g_fork.evJ, 0);
}